// round 14
// baseline (speedup 1.0000x reference)
#include <cuda_runtime.h>
#include <cuda_bf16.h>
#include <cstdint>

// Shapes (fixed): N_NODES=8192, K_FRE=2048, K_HIGH=6144, D=512
#define NN 8192
#define KF 2048
#define KH 6144
#define DD 512

// ---------------- scratch (device globals) ----------------------------------
static __device__ __nv_bfloat16 g_WT_hi [DD * DD];
static __device__ __nv_bfloat16 g_WT_lo [DD * DD];
static __device__ __nv_bfloat16 g_preT_hi[DD * NN];
static __device__ __nv_bfloat16 g_preT_lo[DD * NN];
static __device__ __nv_bfloat16 g_t1T_hi [DD * KF];
static __device__ __nv_bfloat16 g_t1T_lo [DD * KF];
static __device__ __nv_bfloat16 g_t3T_hi [DD * KH];
static __device__ __nv_bfloat16 g_t3T_lo [DD * KH];
static __device__ float         g_low   [NN * DD];
static __device__ float         g_alpha [2];

// ---------------- PTX helpers (baseline ISA only) -----------------------------
__device__ __forceinline__ uint32_t smem_u32(const void* p) {
    uint32_t a;
    asm("{ .reg .u64 t; cvta.to.shared.u64 t, %1; cvt.u32.u64 %0, t; }"
        : "=r"(a) : "l"(p));
    return a;
}
__device__ __forceinline__ void ldsm_x4(uint32_t r[4], uint32_t addr) {
    asm volatile("ldmatrix.sync.aligned.m8n8.x4.shared.b16 {%0,%1,%2,%3}, [%4];"
        : "=r"(r[0]), "=r"(r[1]), "=r"(r[2]), "=r"(r[3]) : "r"(addr));
}
__device__ __forceinline__ void mma16816(float c[4], const uint32_t a[4],
                                         uint32_t b0, uint32_t b1) {
    asm volatile("mma.sync.aligned.m16n8k16.row.col.f32.bf16.bf16.f32 "
        "{%0,%1,%2,%3}, {%4,%5,%6,%7}, {%8,%9}, {%0,%1,%2,%3};"
        : "+f"(c[0]), "+f"(c[1]), "+f"(c[2]), "+f"(c[3])
        : "r"(a[0]), "r"(a[1]), "r"(a[2]), "r"(a[3]), "r"(b0), "r"(b1));
}
__device__ __forceinline__ void cp16(uint32_t saddr, const void* g) {
    asm volatile("cp.async.cg.shared.global [%0], [%1], 16;" :: "r"(saddr), "l"(g));
}
#define CP_COMMIT()  asm volatile("cp.async.commit_group;" ::: "memory")
#define CP_WAIT1()   asm volatile("cp.async.wait_group 1;" ::: "memory")
#define CP_WAIT0()   asm volatile("cp.async.wait_group 0;" ::: "memory")

// ---------------- small kernels ------------------------------------------------
// W [512,512] -> WT hi/lo; block (0,0) thread 0 also computes softmax(alpha).
__global__ void wt_split_kernel(const float* __restrict__ W,
                                const float* __restrict__ alpha) {
    if (blockIdx.x == 0 && blockIdx.y == 0 &&
        threadIdx.x == 0 && threadIdx.y == 0) {
        float a0 = alpha[0], a1 = alpha[1];
        float m = fmaxf(a0, a1);
        float e0 = expf(a0 - m), e1 = expf(a1 - m);
        float inv = 1.0f / (e0 + e1);
        g_alpha[0] = e0 * inv;
        g_alpha[1] = e1 * inv;
    }
    __shared__ float t[32][33];
    int bx = blockIdx.x * 32, by = blockIdx.y * 32;
    int tx = threadIdx.x, ty = threadIdx.y;
    t[ty][tx] = W[(size_t)(by + ty) * DD + bx + tx];
    __syncthreads();
    float v = t[tx][ty];
    int n = bx + ty, k = by + tx;
    __nv_bfloat16 h = __float2bfloat16(v);
    float lv = v - __bfloat162float(h);
    g_WT_hi[(size_t)n * DD + k] = h;
    g_WT_lo[(size_t)n * DD + k] = __float2bfloat16(lv);
}

// ---------------- split-bf16 mma.sync GEMM --------------------------------------
// C[M,512] = A[M,K](fp32) @ Bt[512,K]^T (bf16 hi/lo).
// CTA 256x128, 512 threads (16 warps), warp tile 16x128, kc=64, 2-stage.
// NEW vs R13: cadence de-phasing — odd warps run the ks loop reversed, and
// warp pairs rotate the B-chunk start offset, so warps on one SMSP hit their
// ldsm-wait windows at different times (covers each other's gaps).
// MODE 0: write C^T split bf16 into (CThi1,CTlo1), ld1
// MODE 3: rows < M1 -> (CThi1,CTlo1,ld1); rows >= M1 -> (CThi2,CTlo2,ld2), row-M1
// MODE 1: Cf = alpha[aidx]*C
// MODE 2: Cf = relu(max(alpha[aidx]*C, other) + bias)
#define CTA_M 256
#define CTA_N 128
#define OFF_A32 0          // 256 x 64 fp32 = 64 KB
#define OFF_BH  65536      // 128 x 64 bf16 = 16 KB
#define OFF_BL  81920      // 16 KB
#define STAGE   98304
#define SMEM_TOTAL (2 * STAGE)   // 192 KB

template<int MODE>
__global__ __launch_bounds__(512, 1)
void gemm_mma(const float* __restrict__ A1, const float* __restrict__ A2, int M1,
              const __nv_bfloat16* __restrict__ Bhi,
              const __nv_bfloat16* __restrict__ Blo,
              int K,
              float* __restrict__ Cf,
              __nv_bfloat16* __restrict__ CThi1, __nv_bfloat16* __restrict__ CTlo1, int ld1,
              __nv_bfloat16* __restrict__ CThi2, __nv_bfloat16* __restrict__ CTlo2, int ld2,
              int aidx, const float* __restrict__ other,
              const float* __restrict__ bias)
{
    extern __shared__ char smem[];
    const uint32_t sb = smem_u32(smem);
    const int tid = threadIdx.x;
    const int wid = tid >> 5, lid = tid & 31;
    const int brow = blockIdx.y * CTA_M, bcol = blockIdx.x * CTA_N;
    const int wm = wid * 16;                 // 16 warps, one 16-row band each
    const int grp = lid >> 2, ctid = lid & 3;
    const int kss   = wid & 1;               // ks-order reversal for odd warps
    const int crot  = (wid >> 1) & 3;        // B-chunk start rotation per warp pair

    const float* Abase;
    if (MODE == 3 && brow >= M1) Abase = A2 + (size_t)(brow - M1) * K;
    else                         Abase = A1 + (size_t)brow * K;

    // B ldmatrix lane geometry (128B rows, XOR swizzle)
    const int lb_row = (lid & 7) + ((lid >> 4) << 3);
    const int lb_col = ((lid >> 3) & 1) << 4;

    float acc[16][4];
    #pragma unroll
    for (int j = 0; j < 16; j++)
        #pragma unroll
        for (int q = 0; q < 4; q++) acc[j][q] = 0.0f;

    const int nt = K >> 6;

    // A fp32: 256 rows x 64 f32 = 4096 16B-chunks; 8/thread.
    // B: 128 rows x 64 bf16 (hi+lo) = 1024 chunks each; 2/thread each.
    #define CPA(sidx, kt) do { \
        uint32_t abse = sb + (uint32_t)(sidx) * STAGE; \
        _Pragma("unroll") \
        for (int r = 0; r < 8; r++) { \
            int idx = tid + (r << 9); \
            int row = idx >> 4, c = idx & 15; \
            uint32_t dst = abse + OFF_A32 + row * 256 + (uint32_t)((c ^ ((row & 7) << 1)) << 4); \
            cp16(dst, Abase + (size_t)row * K + (kt) + (c << 2)); \
        } \
        _Pragma("unroll") \
        for (int r = 0; r < 2; r++) { \
            int idx = tid + (r << 9); \
            int row = idx >> 3, c = idx & 7; \
            uint32_t off = (uint32_t)(row * 128 + ((c << 4) ^ ((row & 7) << 4))); \
            size_t g = (size_t)(bcol + row) * K + (kt) + (c << 3); \
            cp16(abse + OFF_BH + off, Bhi + g); \
            cp16(abse + OFF_BL + off, Blo + g); \
        } } while (0)

    // ---- prologue: fill both stages ----
    CPA(0, 0);  CP_COMMIT();
    CPA(1, 64); CP_COMMIT();

    for (int it = 0; it < nt; it++) {
        const int cs = it & 1;
        const uint32_t cbase = sb + (uint32_t)cs * STAGE;
        if (it + 1 < nt) { CP_WAIT1(); } else { CP_WAIT0(); }
        __syncthreads();

        #pragma unroll
        for (int s = 0; s < 4; s++) {
            const int ks = kss ? (3 - s) : s;     // reversed order for odd warps
            // ---- A fragment (m16k16): LDS.64 fp32 pair -> split bf16 hi/lo ----
            uint32_t ah[4], al[4];
            {
                const int r0 = wm + grp;
                #pragma unroll
                for (int u = 0; u < 4; u++) {
                    const int rr = r0 + (u & 1) * 8;
                    const int kk = ks * 16 + ctid * 2 + (u >> 1) * 8;
                    uint32_t addr = cbase + OFF_A32 + rr * 256 +
                        (uint32_t)(((((kk >> 2) ^ ((rr & 7) << 1))) << 4) | ((kk & 3) << 2));
                    float f0, f1;
                    asm volatile("ld.shared.v2.f32 {%0,%1}, [%2];"
                                 : "=f"(f0), "=f"(f1) : "r"(addr));
                    uint32_t h;
                    asm("cvt.rn.bf16x2.f32 %0, %1, %2;" : "=r"(h) : "f"(f1), "f"(f0));
                    float h0 = __uint_as_float(h << 16);
                    float h1 = __uint_as_float(h & 0xFFFF0000u);
                    float l0 = f0 - h0, l1 = f1 - h1;
                    uint32_t l;
                    asm("cvt.rn.bf16x2.f32 %0, %1, %2;" : "=r"(l) : "f"(l1), "f"(l0));
                    ah[u] = h; al[u] = l;
                }
            }
            // ---- B: n128 in 4 chunks of n32, start offset rotated per warp pair ----
            #pragma unroll
            for (int c0i = 0; c0i < 4; c0i++) {
                const int c = (c0i + crot) & 3;
                uint32_t bh[2][4], bl[2][4];
                #pragma unroll
                for (int p = 0; p < 2; p++) {
                    const int prow = lb_row + (c * 2 + p) * 16;
                    uint32_t boff = (uint32_t)(prow * 128 +
                                     ((lb_col + ks * 32) ^ ((prow & 7) << 4)));
                    ldsm_x4(bh[p], cbase + OFF_BH + boff);
                    ldsm_x4(bl[p], cbase + OFF_BL + boff);
                }
                // term-major (R13): 4 independent accumulators per term
                #pragma unroll
                for (int p = 0; p < 2; p++)
                    #pragma unroll
                    for (int h = 0; h < 2; h++)
                        mma16816(acc[c * 4 + p * 2 + h], ah,
                                 bh[p][h * 2], bh[p][h * 2 + 1]);
                #pragma unroll
                for (int p = 0; p < 2; p++)
                    #pragma unroll
                    for (int h = 0; h < 2; h++)
                        mma16816(acc[c * 4 + p * 2 + h], al,
                                 bh[p][h * 2], bh[p][h * 2 + 1]);
                #pragma unroll
                for (int p = 0; p < 2; p++)
                    #pragma unroll
                    for (int h = 0; h < 2; h++)
                        mma16816(acc[c * 4 + p * 2 + h], ah,
                                 bl[p][h * 2], bl[p][h * 2 + 1]);
            }
        }

        __syncthreads();
        if (it + 2 < nt) {
            CPA(cs, (it + 2) << 6);
            CP_COMMIT();
        }
    }

    // ---- epilogue ----
    if (MODE == 0 || MODE == 3) {
        #pragma unroll
        for (int j = 0; j < 16; j++) {
            const int c0 = bcol + j * 8 + ctid * 2;
            #pragma unroll
            for (int q = 0; q < 4; q++) {
                const int mm = brow + wm + grp + (q >> 1) * 8;
                const int cc = c0 + (q & 1);
                float v = acc[j][q];
                __nv_bfloat16 h = __float2bfloat16(v);
                __nv_bfloat16 l = __float2bfloat16(v - __bfloat162float(h));
                if (MODE == 0 || mm < M1) {
                    CThi1[(size_t)cc * ld1 + mm] = h;
                    CTlo1[(size_t)cc * ld1 + mm] = l;
                } else {
                    CThi2[(size_t)cc * ld2 + (mm - M1)] = h;
                    CTlo2[(size_t)cc * ld2 + (mm - M1)] = l;
                }
            }
        }
    } else {
        const float as = g_alpha[aidx];
        const int m0 = brow + wm + grp;
        #pragma unroll
        for (int j = 0; j < 16; j++) {
            const int c0 = bcol + j * 8 + ctid * 2;
            if (MODE == 1) {
                float2 v0 = make_float2(as * acc[j][0], as * acc[j][1]);
                float2 v1 = make_float2(as * acc[j][2], as * acc[j][3]);
                *reinterpret_cast<float2*>(Cf + (size_t)m0 * DD + c0) = v0;
                *reinterpret_cast<float2*>(Cf + (size_t)(m0 + 8) * DD + c0) = v1;
            } else {
                float2 o0 = *reinterpret_cast<const float2*>(other + (size_t)m0 * DD + c0);
                float2 o1 = *reinterpret_cast<const float2*>(other + (size_t)(m0 + 8) * DD + c0);
                float2 bb = *reinterpret_cast<const float2*>(bias + c0);
                float2 v0, v1;
                v0.x = fmaxf(fmaxf(as * acc[j][0], o0.x) + bb.x, 0.0f);
                v0.y = fmaxf(fmaxf(as * acc[j][1], o0.y) + bb.y, 0.0f);
                v1.x = fmaxf(fmaxf(as * acc[j][2], o1.x) + bb.x, 0.0f);
                v1.y = fmaxf(fmaxf(as * acc[j][3], o1.y) + bb.y, 0.0f);
                *reinterpret_cast<float2*>(Cf + (size_t)m0 * DD + c0) = v0;
                *reinterpret_cast<float2*>(Cf + (size_t)(m0 + 8) * DD + c0) = v1;
            }
        }
    }
    #undef CPA
}

// ---------------- host launch ----------------------------------------------------
extern "C" void kernel_launch(void* const* d_in, const int* in_sizes, int n_in,
                              void* d_out, int out_size)
{
    const float* x     = (const float*)d_in[0];
    const float* W     = (const float*)d_in[1];
    const float* alpha = (const float*)d_in[2];
    const float* bias  = (const float*)d_in[3];
    const float* s0    = (const float*)d_in[4];
    const float* s1    = (const float*)d_in[5];
    const float* s2    = (const float*)d_in[6];
    const float* s3    = (const float*)d_in[7];
    float* out = (float*)d_out;

    __nv_bfloat16 *WTh, *WTl, *pTh, *pTl, *t1h, *t1l, *t3h, *t3l;
    float* low;
    cudaGetSymbolAddress((void**)&WTh, g_WT_hi);
    cudaGetSymbolAddress((void**)&WTl, g_WT_lo);
    cudaGetSymbolAddress((void**)&pTh, g_preT_hi);
    cudaGetSymbolAddress((void**)&pTl, g_preT_lo);
    cudaGetSymbolAddress((void**)&t1h, g_t1T_hi);
    cudaGetSymbolAddress((void**)&t1l, g_t1T_lo);
    cudaGetSymbolAddress((void**)&t3h, g_t3T_hi);
    cudaGetSymbolAddress((void**)&t3l, g_t3T_lo);
    cudaGetSymbolAddress((void**)&low, g_low);

    static bool attr_done = false;
    if (!attr_done) {
        cudaFuncSetAttribute(gemm_mma<0>, cudaFuncAttributeMaxDynamicSharedMemorySize, SMEM_TOTAL);
        cudaFuncSetAttribute(gemm_mma<1>, cudaFuncAttributeMaxDynamicSharedMemorySize, SMEM_TOTAL);
        cudaFuncSetAttribute(gemm_mma<2>, cudaFuncAttributeMaxDynamicSharedMemorySize, SMEM_TOTAL);
        cudaFuncSetAttribute(gemm_mma<3>, cudaFuncAttributeMaxDynamicSharedMemorySize, SMEM_TOTAL);
        attr_done = true;
    }

    wt_split_kernel<<<dim3(16, 16), dim3(32, 32)>>>(W, alpha);

    const dim3 grid(DD / CTA_N, NN / CTA_M);   // (4, 32) = 128 CTAs

    // pre^T = (x @ W)^T (split bf16)
    gemm_mma<0><<<grid, 512, SMEM_TOTAL>>>(
        x, nullptr, NN, WTh, WTl, DD,
        nullptr, pTh, pTl, NN, nullptr, nullptr, 0, 0, nullptr, nullptr);
    // merged: t1^T (rows<2048 from s1) + t3^T (rows>=2048 from s3)
    gemm_mma<3><<<grid, 512, SMEM_TOTAL>>>(
        s1, s3, KF, pTh, pTl, NN,
        nullptr, t1h, t1l, KF, t3h, t3l, KH, 0, nullptr, nullptr);
    // low = a0 * (s0 @ t1)
    gemm_mma<1><<<grid, 512, SMEM_TOTAL>>>(
        s0, nullptr, NN, t1h, t1l, KF,
        low, nullptr, nullptr, 0, nullptr, nullptr, 0, 0, nullptr, nullptr);
    // out = relu(max(a1*(s2 @ t3), low) + bias)
    gemm_mma<2><<<grid, 512, SMEM_TOTAL>>>(
        s2, nullptr, NN, t3h, t3l, KH,
        out, nullptr, nullptr, 0, nullptr, nullptr, 1, 1, low, bias);
}

// round 15
// speedup vs baseline: 4.2471x; 4.2471x over previous
#include <cuda_runtime.h>
#include <cuda_fp16.h>
#include <cstdint>

// Shapes (fixed): N_NODES=8192, K_FRE=2048, K_HIGH=6144, D=512
#define NN 8192
#define KF 2048
#define KH 6144
#define DD 512

// ---------------- scratch (device globals) ----------------------------------
static __device__ __half g_WT  [DD * DD];   // W^T  fp16
static __device__ __half g_preT[DD * NN];   // (x@W)^T fp16
static __device__ __half g_t1T [DD * KF];   // (s1@pre)^T fp16
static __device__ __half g_t3T [DD * KH];   // (s3@pre)^T fp16
static __device__ float  g_low [NN * DD];
static __device__ float  g_alpha[2];

// ---------------- PTX helpers (baseline ISA only) -----------------------------
__device__ __forceinline__ uint32_t smem_u32(const void* p) {
    uint32_t a;
    asm("{ .reg .u64 t; cvta.to.shared.u64 t, %1; cvt.u32.u64 %0, t; }"
        : "=r"(a) : "l"(p));
    return a;
}
__device__ __forceinline__ void ldsm_x4(uint32_t r[4], uint32_t addr) {
    asm volatile("ldmatrix.sync.aligned.m8n8.x4.shared.b16 {%0,%1,%2,%3}, [%4];"
        : "=r"(r[0]), "=r"(r[1]), "=r"(r[2]), "=r"(r[3]) : "r"(addr));
}
// fp16 inputs, fp32 accumulate
__device__ __forceinline__ void mma16816(float c[4], const uint32_t a[4],
                                         uint32_t b0, uint32_t b1) {
    asm volatile("mma.sync.aligned.m16n8k16.row.col.f32.f16.f16.f32 "
        "{%0,%1,%2,%3}, {%4,%5,%6,%7}, {%8,%9}, {%0,%1,%2,%3};"
        : "+f"(c[0]), "+f"(c[1]), "+f"(c[2]), "+f"(c[3])
        : "r"(a[0]), "r"(a[1]), "r"(a[2]), "r"(a[3]), "r"(b0), "r"(b1));
}
__device__ __forceinline__ void cp16(uint32_t saddr, const void* g) {
    asm volatile("cp.async.cg.shared.global [%0], [%1], 16;" :: "r"(saddr), "l"(g));
}
#define CP_COMMIT()  asm volatile("cp.async.commit_group;" ::: "memory")
#define CP_WAIT1()   asm volatile("cp.async.wait_group 1;" ::: "memory")
#define CP_WAIT0()   asm volatile("cp.async.wait_group 0;" ::: "memory")

// ---------------- small kernels ------------------------------------------------
// W [512,512] -> WT fp16; block (0,0) thread 0 also computes softmax(alpha).
__global__ void wt_split_kernel(const float* __restrict__ W,
                                const float* __restrict__ alpha) {
    if (blockIdx.x == 0 && blockIdx.y == 0 &&
        threadIdx.x == 0 && threadIdx.y == 0) {
        float a0 = alpha[0], a1 = alpha[1];
        float m = fmaxf(a0, a1);
        float e0 = expf(a0 - m), e1 = expf(a1 - m);
        float inv = 1.0f / (e0 + e1);
        g_alpha[0] = e0 * inv;
        g_alpha[1] = e1 * inv;
    }
    __shared__ float t[32][33];
    int bx = blockIdx.x * 32, by = blockIdx.y * 32;
    int tx = threadIdx.x, ty = threadIdx.y;
    t[ty][tx] = W[(size_t)(by + ty) * DD + bx + tx];
    __syncthreads();
    float v = t[tx][ty];
    int n = bx + ty, k = by + tx;
    g_WT[(size_t)n * DD + k] = __float2half(v);
}

// ---------------- split-fp16 2-product mma.sync GEMM ---------------------------
// C[M,512] = A[M,K](fp32) @ Bt[512,K]^T (fp16).
// A split into fp16 hi/lo at fragment build (2-term, ~23-bit); B single fp16.
// C ≈ Ah·Bh + Al·Bh  (2 MMAs per k16 instead of 3 — the MMA-throughput floor
// is the binder on sm_103a, so this is a direct 1/3 cut in floor time).
// CTA 256x128, 512 threads (16 warps), warp tile 16x128, kc=64, 2-stage.
// MODE 0: write C^T fp16 into CT1, ld1
// MODE 3: rows < M1 -> (CT1,ld1); rows >= M1 -> (CT2,ld2) at row-M1
// MODE 1: Cf = alpha[aidx]*C
// MODE 2: Cf = relu(max(alpha[aidx]*C, other) + bias)
#define CTA_M 256
#define CTA_N 128
#define OFF_A32 0          // 256 x 64 fp32 = 64 KB
#define OFF_B   65536      // 128 x 64 fp16 = 16 KB
#define STAGE   81920
#define SMEM_TOTAL (2 * STAGE)   // 160 KB

template<int MODE>
__global__ __launch_bounds__(512, 1)
void gemm_mma(const float* __restrict__ A1, const float* __restrict__ A2, int M1,
              const __half* __restrict__ Bh,
              int K,
              float* __restrict__ Cf,
              __half* __restrict__ CT1, int ld1,
              __half* __restrict__ CT2, int ld2,
              int aidx, const float* __restrict__ other,
              const float* __restrict__ bias)
{
    extern __shared__ char smem[];
    const uint32_t sb = smem_u32(smem);
    const int tid = threadIdx.x;
    const int wid = tid >> 5, lid = tid & 31;
    const int brow = blockIdx.y * CTA_M, bcol = blockIdx.x * CTA_N;
    const int wm = wid * 16;                 // 16 warps, one 16-row band each
    const int grp = lid >> 2, ctid = lid & 3;

    const float* Abase;
    if (MODE == 3 && brow >= M1) Abase = A2 + (size_t)(brow - M1) * K;
    else                         Abase = A1 + (size_t)brow * K;

    // B ldmatrix lane geometry (128B rows, XOR swizzle)
    const int lb_row = (lid & 7) + ((lid >> 4) << 3);
    const int lb_col = ((lid >> 3) & 1) << 4;

    float acc[16][4];
    #pragma unroll
    for (int j = 0; j < 16; j++)
        #pragma unroll
        for (int q = 0; q < 4; q++) acc[j][q] = 0.0f;

    const int nt = K >> 6;

    // A fp32: 256 rows x 64 f32 = 4096 16B-chunks; 8/thread.
    // B fp16: 128 rows x 64 halves (128B/row) = 1024 chunks; 2/thread.
    #define CPA(sidx, kt) do { \
        uint32_t abse = sb + (uint32_t)(sidx) * STAGE; \
        _Pragma("unroll") \
        for (int r = 0; r < 8; r++) { \
            int idx = tid + (r << 9); \
            int row = idx >> 4, c = idx & 15; \
            uint32_t dst = abse + OFF_A32 + row * 256 + (uint32_t)((c ^ ((row & 7) << 1)) << 4); \
            cp16(dst, Abase + (size_t)row * K + (kt) + (c << 2)); \
        } \
        _Pragma("unroll") \
        for (int r = 0; r < 2; r++) { \
            int idx = tid + (r << 9); \
            int row = idx >> 3, c = idx & 7; \
            uint32_t dst = abse + OFF_B + row * 128 + (uint32_t)((c ^ (row & 7)) << 4); \
            cp16(dst, Bh + (size_t)(bcol + row) * K + (kt) + (c << 3)); \
        } } while (0)

    // ---- prologue: fill both stages ----
    CPA(0, 0);  CP_COMMIT();
    CPA(1, 64); CP_COMMIT();

    for (int it = 0; it < nt; it++) {
        const int cs = it & 1;
        const uint32_t cbase = sb + (uint32_t)cs * STAGE;
        if (it + 1 < nt) { CP_WAIT1(); } else { CP_WAIT0(); }
        __syncthreads();

        #pragma unroll
        for (int ks = 0; ks < 4; ks++) {
            // ---- A fragment (m16k16): LDS.64 fp32 pair -> split fp16 hi/lo ----
            uint32_t ah[4], al[4];
            {
                const int r0 = wm + grp;
                #pragma unroll
                for (int u = 0; u < 4; u++) {
                    const int rr = r0 + (u & 1) * 8;
                    const int kk = ks * 16 + ctid * 2 + (u >> 1) * 8;
                    uint32_t addr = cbase + OFF_A32 + rr * 256 +
                        (uint32_t)(((((kk >> 2) ^ ((rr & 7) << 1))) << 4) | ((kk & 3) << 2));
                    float f0, f1;
                    asm volatile("ld.shared.v2.f32 {%0,%1}, [%2];"
                                 : "=f"(f0), "=f"(f1) : "r"(addr));
                    __half2 hh = __floats2half2_rn(f0, f1);
                    float2 hf = __half22float2(hh);
                    __half2 ll = __floats2half2_rn(f0 - hf.x, f1 - hf.y);
                    ah[u] = reinterpret_cast<uint32_t&>(hh);
                    al[u] = reinterpret_cast<uint32_t&>(ll);
                }
            }
            // ---- B: n128 consumed in 4 chunks of n32; 2-product term-major ----
            #pragma unroll
            for (int c = 0; c < 4; c++) {
                uint32_t bh[2][4];
                #pragma unroll
                for (int p = 0; p < 2; p++) {
                    const int prow = lb_row + (c * 2 + p) * 16;
                    uint32_t boff = (uint32_t)(prow * 128 +
                                     ((lb_col + ks * 32) ^ ((prow & 7) << 4)));
                    ldsm_x4(bh[p], cbase + OFF_B + boff);
                }
                // term 0: Ah x Bh (4 independent accumulators)
                #pragma unroll
                for (int p = 0; p < 2; p++)
                    #pragma unroll
                    for (int h = 0; h < 2; h++)
                        mma16816(acc[c * 4 + p * 2 + h], ah,
                                 bh[p][h * 2], bh[p][h * 2 + 1]);
                // term 1: Al x Bh
                #pragma unroll
                for (int p = 0; p < 2; p++)
                    #pragma unroll
                    for (int h = 0; h < 2; h++)
                        mma16816(acc[c * 4 + p * 2 + h], al,
                                 bh[p][h * 2], bh[p][h * 2 + 1]);
            }
        }

        __syncthreads();
        if (it + 2 < nt) {
            CPA(cs, (it + 2) << 6);
            CP_COMMIT();
        }
    }

    // ---- epilogue ----
    if (MODE == 0 || MODE == 3) {
        #pragma unroll
        for (int j = 0; j < 16; j++) {
            const int c0 = bcol + j * 8 + ctid * 2;
            #pragma unroll
            for (int q = 0; q < 4; q++) {
                const int mm = brow + wm + grp + (q >> 1) * 8;
                const int cc = c0 + (q & 1);
                __half h = __float2half(acc[j][q]);
                if (MODE == 0 || mm < M1) {
                    CT1[(size_t)cc * ld1 + mm] = h;
                } else {
                    CT2[(size_t)cc * ld2 + (mm - M1)] = h;
                }
            }
        }
    } else {
        const float as = g_alpha[aidx];
        const int m0 = brow + wm + grp;
        #pragma unroll
        for (int j = 0; j < 16; j++) {
            const int c0 = bcol + j * 8 + ctid * 2;
            if (MODE == 1) {
                float2 v0 = make_float2(as * acc[j][0], as * acc[j][1]);
                float2 v1 = make_float2(as * acc[j][2], as * acc[j][3]);
                *reinterpret_cast<float2*>(Cf + (size_t)m0 * DD + c0) = v0;
                *reinterpret_cast<float2*>(Cf + (size_t)(m0 + 8) * DD + c0) = v1;
            } else {
                float2 o0 = *reinterpret_cast<const float2*>(other + (size_t)m0 * DD + c0);
                float2 o1 = *reinterpret_cast<const float2*>(other + (size_t)(m0 + 8) * DD + c0);
                float2 bb = *reinterpret_cast<const float2*>(bias + c0);
                float2 v0, v1;
                v0.x = fmaxf(fmaxf(as * acc[j][0], o0.x) + bb.x, 0.0f);
                v0.y = fmaxf(fmaxf(as * acc[j][1], o0.y) + bb.y, 0.0f);
                v1.x = fmaxf(fmaxf(as * acc[j][2], o1.x) + bb.x, 0.0f);
                v1.y = fmaxf(fmaxf(as * acc[j][3], o1.y) + bb.y, 0.0f);
                *reinterpret_cast<float2*>(Cf + (size_t)m0 * DD + c0) = v0;
                *reinterpret_cast<float2*>(Cf + (size_t)(m0 + 8) * DD + c0) = v1;
            }
        }
    }
    #undef CPA
}

// ---------------- host launch ----------------------------------------------------
extern "C" void kernel_launch(void* const* d_in, const int* in_sizes, int n_in,
                              void* d_out, int out_size)
{
    const float* x     = (const float*)d_in[0];
    const float* W     = (const float*)d_in[1];
    const float* alpha = (const float*)d_in[2];
    const float* bias  = (const float*)d_in[3];
    const float* s0    = (const float*)d_in[4];
    const float* s1    = (const float*)d_in[5];
    const float* s2    = (const float*)d_in[6];
    const float* s3    = (const float*)d_in[7];
    float* out = (float*)d_out;

    __half *WT, *pT, *t1, *t3;
    float* low;
    cudaGetSymbolAddress((void**)&WT, g_WT);
    cudaGetSymbolAddress((void**)&pT, g_preT);
    cudaGetSymbolAddress((void**)&t1, g_t1T);
    cudaGetSymbolAddress((void**)&t3, g_t3T);
    cudaGetSymbolAddress((void**)&low, g_low);

    static bool attr_done = false;
    if (!attr_done) {
        cudaFuncSetAttribute(gemm_mma<0>, cudaFuncAttributeMaxDynamicSharedMemorySize, SMEM_TOTAL);
        cudaFuncSetAttribute(gemm_mma<1>, cudaFuncAttributeMaxDynamicSharedMemorySize, SMEM_TOTAL);
        cudaFuncSetAttribute(gemm_mma<2>, cudaFuncAttributeMaxDynamicSharedMemorySize, SMEM_TOTAL);
        cudaFuncSetAttribute(gemm_mma<3>, cudaFuncAttributeMaxDynamicSharedMemorySize, SMEM_TOTAL);
        attr_done = true;
    }

    wt_split_kernel<<<dim3(16, 16), dim3(32, 32)>>>(W, alpha);

    const dim3 grid(DD / CTA_N, NN / CTA_M);   // (4, 32) = 128 CTAs

    // pre^T = (x @ W)^T (fp16)
    gemm_mma<0><<<grid, 512, SMEM_TOTAL>>>(
        x, nullptr, NN, WT, DD,
        nullptr, pT, NN, nullptr, 0, 0, nullptr, nullptr);
    // merged: t1^T (rows<2048 from s1) + t3^T (rows>=2048 from s3)
    gemm_mma<3><<<grid, 512, SMEM_TOTAL>>>(
        s1, s3, KF, pT, NN,
        nullptr, t1, KF, t3, KH, 0, nullptr, nullptr);
    // low = a0 * (s0 @ t1)
    gemm_mma<1><<<grid, 512, SMEM_TOTAL>>>(
        s0, nullptr, NN, t1, KF,
        low, nullptr, 0, nullptr, 0, 0, nullptr, nullptr);
    // out = relu(max(a1*(s2 @ t3), low) + bias)
    gemm_mma<2><<<grid, 512, SMEM_TOTAL>>>(
        s2, nullptr, NN, t3, KH,
        out, nullptr, 0, nullptr, 0, 1, low, bias);
}

// round 16
// speedup vs baseline: 6.4510x; 1.5189x over previous
#include <cuda_runtime.h>
#include <cuda_fp16.h>
#include <cstdint>

// Shapes (fixed): N_NODES=8192, K_FRE=2048, K_HIGH=6144, D=512
#define NN 8192
#define KF 2048
#define KH 6144
#define DD 512

// ---------------- scratch (device globals) ----------------------------------
static __device__ __half g_WT  [DD * DD];   // W^T  fp16
static __device__ __half g_preT[DD * NN];   // (x@W)^T fp16
static __device__ __half g_t1T [DD * KF];   // (s1@pre)^T fp16
static __device__ __half g_t3T [DD * KH];   // (s3@pre)^T fp16
static __device__ float  g_low [NN * DD];
static __device__ float  g_alpha[2];

// ---------------- PTX helpers (baseline ISA only) -----------------------------
__device__ __forceinline__ uint32_t smem_u32(const void* p) {
    uint32_t a;
    asm("{ .reg .u64 t; cvta.to.shared.u64 t, %1; cvt.u32.u64 %0, t; }"
        : "=r"(a) : "l"(p));
    return a;
}
__device__ __forceinline__ void ldsm_x4(uint32_t r[4], uint32_t addr) {
    asm volatile("ldmatrix.sync.aligned.m8n8.x4.shared.b16 {%0,%1,%2,%3}, [%4];"
        : "=r"(r[0]), "=r"(r[1]), "=r"(r[2]), "=r"(r[3]) : "r"(addr));
}
// fp16 inputs, fp32 accumulate
__device__ __forceinline__ void mma16816(float c[4], const uint32_t a[4],
                                         uint32_t b0, uint32_t b1) {
    asm volatile("mma.sync.aligned.m16n8k16.row.col.f32.f16.f16.f32 "
        "{%0,%1,%2,%3}, {%4,%5,%6,%7}, {%8,%9}, {%0,%1,%2,%3};"
        : "+f"(c[0]), "+f"(c[1]), "+f"(c[2]), "+f"(c[3])
        : "r"(a[0]), "r"(a[1]), "r"(a[2]), "r"(a[3]), "r"(b0), "r"(b1));
}
__device__ __forceinline__ void cp16(uint32_t saddr, const void* g) {
    asm volatile("cp.async.cg.shared.global [%0], [%1], 16;" :: "r"(saddr), "l"(g));
}
#define CP_COMMIT()  asm volatile("cp.async.commit_group;" ::: "memory")
#define CP_WAIT1()   asm volatile("cp.async.wait_group 1;" ::: "memory")
#define CP_WAIT0()   asm volatile("cp.async.wait_group 0;" ::: "memory")

// ---------------- small kernels ------------------------------------------------
// W [512,512] -> WT fp16; block (0,0) thread 0 also computes softmax(alpha).
__global__ void wt_split_kernel(const float* __restrict__ W,
                                const float* __restrict__ alpha) {
    if (blockIdx.x == 0 && blockIdx.y == 0 &&
        threadIdx.x == 0 && threadIdx.y == 0) {
        float a0 = alpha[0], a1 = alpha[1];
        float m = fmaxf(a0, a1);
        float e0 = expf(a0 - m), e1 = expf(a1 - m);
        float inv = 1.0f / (e0 + e1);
        g_alpha[0] = e0 * inv;
        g_alpha[1] = e1 * inv;
    }
    __shared__ float t[32][33];
    int bx = blockIdx.x * 32, by = blockIdx.y * 32;
    int tx = threadIdx.x, ty = threadIdx.y;
    t[ty][tx] = W[(size_t)(by + ty) * DD + bx + tx];
    __syncthreads();
    float v = t[tx][ty];
    int n = bx + ty, k = by + tx;
    g_WT[(size_t)n * DD + k] = __float2half(v);
}

// ---------------- single-product fp16 mma.sync GEMM ----------------------------
// C[M,512] = A[M,K](fp32 -> fp16 at fragment build) @ Bt[512,K]^T (fp16).
// ONE MMA per k16 per n8 tile — the MMA-throughput floor (rt~12 cyc) is the
// binder on sm_103a, so MMA count is the only thing that matters.
// CTA 256x128, 512 threads (16 warps), warp tile 16x128, kc=64, 2-stage.
// MODE 0: write C^T fp16 into CT1, ld1
// MODE 3: rows < M1 -> (CT1,ld1); rows >= M1 -> (CT2,ld2) at row-M1
// MODE 1: Cf = alpha[aidx]*C
// MODE 2: Cf = relu(max(alpha[aidx]*C, other) + bias)
#define CTA_M 256
#define CTA_N 128
#define OFF_A32 0          // 256 x 64 fp32 = 64 KB
#define OFF_B   65536      // 128 x 64 fp16 = 16 KB
#define STAGE   81920
#define SMEM_TOTAL (2 * STAGE)   // 160 KB

template<int MODE>
__global__ __launch_bounds__(512, 1)
void gemm_mma(const float* __restrict__ A1, const float* __restrict__ A2, int M1,
              const __half* __restrict__ Bh,
              int K,
              float* __restrict__ Cf,
              __half* __restrict__ CT1, int ld1,
              __half* __restrict__ CT2, int ld2,
              int aidx, const float* __restrict__ other,
              const float* __restrict__ bias)
{
    extern __shared__ char smem[];
    const uint32_t sb = smem_u32(smem);
    const int tid = threadIdx.x;
    const int wid = tid >> 5, lid = tid & 31;
    const int brow = blockIdx.y * CTA_M, bcol = blockIdx.x * CTA_N;
    const int wm = wid * 16;                 // 16 warps, one 16-row band each
    const int grp = lid >> 2, ctid = lid & 3;

    const float* Abase;
    if (MODE == 3 && brow >= M1) Abase = A2 + (size_t)(brow - M1) * K;
    else                         Abase = A1 + (size_t)brow * K;

    // B ldmatrix lane geometry (128B rows, XOR swizzle)
    const int lb_row = (lid & 7) + ((lid >> 4) << 3);
    const int lb_col = ((lid >> 3) & 1) << 4;

    float acc[16][4];
    #pragma unroll
    for (int j = 0; j < 16; j++)
        #pragma unroll
        for (int q = 0; q < 4; q++) acc[j][q] = 0.0f;

    const int nt = K >> 6;

    // A fp32: 256 rows x 64 f32 = 4096 16B-chunks; 8/thread.
    // B fp16: 128 rows x 64 halves (128B/row) = 1024 chunks; 2/thread.
    #define CPA(sidx, kt) do { \
        uint32_t abse = sb + (uint32_t)(sidx) * STAGE; \
        _Pragma("unroll") \
        for (int r = 0; r < 8; r++) { \
            int idx = tid + (r << 9); \
            int row = idx >> 4, c = idx & 15; \
            uint32_t dst = abse + OFF_A32 + row * 256 + (uint32_t)((c ^ ((row & 7) << 1)) << 4); \
            cp16(dst, Abase + (size_t)row * K + (kt) + (c << 2)); \
        } \
        _Pragma("unroll") \
        for (int r = 0; r < 2; r++) { \
            int idx = tid + (r << 9); \
            int row = idx >> 3, c = idx & 7; \
            uint32_t dst = abse + OFF_B + row * 128 + (uint32_t)((c ^ (row & 7)) << 4); \
            cp16(dst, Bh + (size_t)(bcol + row) * K + (kt) + (c << 3)); \
        } } while (0)

    // ---- prologue: fill both stages ----
    CPA(0, 0);  CP_COMMIT();
    CPA(1, 64); CP_COMMIT();

    for (int it = 0; it < nt; it++) {
        const int cs = it & 1;
        const uint32_t cbase = sb + (uint32_t)cs * STAGE;
        if (it + 1 < nt) { CP_WAIT1(); } else { CP_WAIT0(); }
        __syncthreads();

        #pragma unroll
        for (int ks = 0; ks < 4; ks++) {
            // ---- A fragment (m16k16): LDS.64 fp32 pair -> fp16 ----
            uint32_t ah[4];
            {
                const int r0 = wm + grp;
                #pragma unroll
                for (int u = 0; u < 4; u++) {
                    const int rr = r0 + (u & 1) * 8;
                    const int kk = ks * 16 + ctid * 2 + (u >> 1) * 8;
                    uint32_t addr = cbase + OFF_A32 + rr * 256 +
                        (uint32_t)(((((kk >> 2) ^ ((rr & 7) << 1))) << 4) | ((kk & 3) << 2));
                    float f0, f1;
                    asm volatile("ld.shared.v2.f32 {%0,%1}, [%2];"
                                 : "=f"(f0), "=f"(f1) : "r"(addr));
                    __half2 hh = __floats2half2_rn(f0, f1);
                    ah[u] = reinterpret_cast<uint32_t&>(hh);
                }
            }
            // ---- B: n128 consumed in 4 chunks of n32; single product ----
            #pragma unroll
            for (int c = 0; c < 4; c++) {
                uint32_t bh[2][4];
                #pragma unroll
                for (int p = 0; p < 2; p++) {
                    const int prow = lb_row + (c * 2 + p) * 16;
                    uint32_t boff = (uint32_t)(prow * 128 +
                                     ((lb_col + ks * 32) ^ ((prow & 7) << 4)));
                    ldsm_x4(bh[p], cbase + OFF_B + boff);
                }
                #pragma unroll
                for (int p = 0; p < 2; p++)
                    #pragma unroll
                    for (int h = 0; h < 2; h++)
                        mma16816(acc[c * 4 + p * 2 + h], ah,
                                 bh[p][h * 2], bh[p][h * 2 + 1]);
            }
        }

        __syncthreads();
        if (it + 2 < nt) {
            CPA(cs, (it + 2) << 6);
            CP_COMMIT();
        }
    }

    // ---- epilogue ----
    if (MODE == 0 || MODE == 3) {
        #pragma unroll
        for (int j = 0; j < 16; j++) {
            const int c0 = bcol + j * 8 + ctid * 2;
            #pragma unroll
            for (int q = 0; q < 4; q++) {
                const int mm = brow + wm + grp + (q >> 1) * 8;
                const int cc = c0 + (q & 1);
                __half h = __float2half(acc[j][q]);
                if (MODE == 0 || mm < M1) {
                    CT1[(size_t)cc * ld1 + mm] = h;
                } else {
                    CT2[(size_t)cc * ld2 + (mm - M1)] = h;
                }
            }
        }
    } else {
        const float as = g_alpha[aidx];
        const int m0 = brow + wm + grp;
        #pragma unroll
        for (int j = 0; j < 16; j++) {
            const int c0 = bcol + j * 8 + ctid * 2;
            if (MODE == 1) {
                float2 v0 = make_float2(as * acc[j][0], as * acc[j][1]);
                float2 v1 = make_float2(as * acc[j][2], as * acc[j][3]);
                *reinterpret_cast<float2*>(Cf + (size_t)m0 * DD + c0) = v0;
                *reinterpret_cast<float2*>(Cf + (size_t)(m0 + 8) * DD + c0) = v1;
            } else {
                float2 o0 = *reinterpret_cast<const float2*>(other + (size_t)m0 * DD + c0);
                float2 o1 = *reinterpret_cast<const float2*>(other + (size_t)(m0 + 8) * DD + c0);
                float2 bb = *reinterpret_cast<const float2*>(bias + c0);
                float2 v0, v1;
                v0.x = fmaxf(fmaxf(as * acc[j][0], o0.x) + bb.x, 0.0f);
                v0.y = fmaxf(fmaxf(as * acc[j][1], o0.y) + bb.y, 0.0f);
                v1.x = fmaxf(fmaxf(as * acc[j][2], o1.x) + bb.x, 0.0f);
                v1.y = fmaxf(fmaxf(as * acc[j][3], o1.y) + bb.y, 0.0f);
                *reinterpret_cast<float2*>(Cf + (size_t)m0 * DD + c0) = v0;
                *reinterpret_cast<float2*>(Cf + (size_t)(m0 + 8) * DD + c0) = v1;
            }
        }
    }
    #undef CPA
}

// ---------------- host launch ----------------------------------------------------
extern "C" void kernel_launch(void* const* d_in, const int* in_sizes, int n_in,
                              void* d_out, int out_size)
{
    const float* x     = (const float*)d_in[0];
    const float* W     = (const float*)d_in[1];
    const float* alpha = (const float*)d_in[2];
    const float* bias  = (const float*)d_in[3];
    const float* s0    = (const float*)d_in[4];
    const float* s1    = (const float*)d_in[5];
    const float* s2    = (const float*)d_in[6];
    const float* s3    = (const float*)d_in[7];
    float* out = (float*)d_out;

    __half *WT, *pT, *t1, *t3;
    float* low;
    cudaGetSymbolAddress((void**)&WT, g_WT);
    cudaGetSymbolAddress((void**)&pT, g_preT);
    cudaGetSymbolAddress((void**)&t1, g_t1T);
    cudaGetSymbolAddress((void**)&t3, g_t3T);
    cudaGetSymbolAddress((void**)&low, g_low);

    static bool attr_done = false;
    if (!attr_done) {
        cudaFuncSetAttribute(gemm_mma<0>, cudaFuncAttributeMaxDynamicSharedMemorySize, SMEM_TOTAL);
        cudaFuncSetAttribute(gemm_mma<1>, cudaFuncAttributeMaxDynamicSharedMemorySize, SMEM_TOTAL);
        cudaFuncSetAttribute(gemm_mma<2>, cudaFuncAttributeMaxDynamicSharedMemorySize, SMEM_TOTAL);
        cudaFuncSetAttribute(gemm_mma<3>, cudaFuncAttributeMaxDynamicSharedMemorySize, SMEM_TOTAL);
        attr_done = true;
    }

    wt_split_kernel<<<dim3(16, 16), dim3(32, 32)>>>(W, alpha);

    const dim3 grid(DD / CTA_N, NN / CTA_M);   // (4, 32) = 128 CTAs

    // pre^T = (x @ W)^T (fp16)
    gemm_mma<0><<<grid, 512, SMEM_TOTAL>>>(
        x, nullptr, NN, WT, DD,
        nullptr, pT, NN, nullptr, 0, 0, nullptr, nullptr);
    // merged: t1^T (rows<2048 from s1) + t3^T (rows>=2048 from s3)
    gemm_mma<3><<<grid, 512, SMEM_TOTAL>>>(
        s1, s3, KF, pT, NN,
        nullptr, t1, KF, t3, KH, 0, nullptr, nullptr);
    // low = a0 * (s0 @ t1)
    gemm_mma<1><<<grid, 512, SMEM_TOTAL>>>(
        s0, nullptr, NN, t1, KF,
        low, nullptr, 0, nullptr, 0, 0, nullptr, nullptr);
    // out = relu(max(a1*(s2 @ t3), low) + bias)
    gemm_mma<2><<<grid, 512, SMEM_TOTAL>>>(
        s2, nullptr, NN, t3, KH,
        out, nullptr, 0, nullptr, 0, 1, low, bias);
}

// round 17
// speedup vs baseline: 6.4800x; 1.0045x over previous
#include <cuda_runtime.h>
#include <cuda_fp16.h>
#include <cstdint>

// Shapes (fixed): N_NODES=8192, K_FRE=2048, K_HIGH=6144, D=512
#define NN 8192
#define KF 2048
#define KH 6144
#define DD 512

// ---------------- scratch (device globals) ----------------------------------
static __device__ __half g_WT  [DD * DD];   // W^T  fp16
static __device__ __half g_preT[DD * NN];   // (x@W)^T fp16
static __device__ __half g_t1T [DD * KF];   // (s1@pre)^T fp16
static __device__ __half g_t3T [DD * KH];   // (s3@pre)^T fp16
static __device__ float  g_alpha[2];

// ---------------- PTX helpers (baseline ISA only) -----------------------------
__device__ __forceinline__ uint32_t smem_u32(const void* p) {
    uint32_t a;
    asm("{ .reg .u64 t; cvta.to.shared.u64 t, %1; cvt.u32.u64 %0, t; }"
        : "=r"(a) : "l"(p));
    return a;
}
__device__ __forceinline__ void ldsm_x4(uint32_t r[4], uint32_t addr) {
    asm volatile("ldmatrix.sync.aligned.m8n8.x4.shared.b16 {%0,%1,%2,%3}, [%4];"
        : "=r"(r[0]), "=r"(r[1]), "=r"(r[2]), "=r"(r[3]) : "r"(addr));
}
// fp16 inputs, fp32 accumulate
__device__ __forceinline__ void mma16816(float c[4], const uint32_t a[4],
                                         uint32_t b0, uint32_t b1) {
    asm volatile("mma.sync.aligned.m16n8k16.row.col.f32.f16.f16.f32 "
        "{%0,%1,%2,%3}, {%4,%5,%6,%7}, {%8,%9}, {%0,%1,%2,%3};"
        : "+f"(c[0]), "+f"(c[1]), "+f"(c[2]), "+f"(c[3])
        : "r"(a[0]), "r"(a[1]), "r"(a[2]), "r"(a[3]), "r"(b0), "r"(b1));
}
__device__ __forceinline__ void cp16(uint32_t saddr, const void* g) {
    asm volatile("cp.async.cg.shared.global [%0], [%1], 16;" :: "r"(saddr), "l"(g));
}
#define CP_COMMIT()  asm volatile("cp.async.commit_group;" ::: "memory")
#define CP_WAIT1()   asm volatile("cp.async.wait_group 1;" ::: "memory")
#define CP_WAIT0()   asm volatile("cp.async.wait_group 0;" ::: "memory")

// ---------------- small kernels ------------------------------------------------
// W [512,512] -> WT fp16; block (0,0) thread 0 also computes softmax(alpha).
__global__ void wt_split_kernel(const float* __restrict__ W,
                                const float* __restrict__ alpha) {
    if (blockIdx.x == 0 && blockIdx.y == 0 &&
        threadIdx.x == 0 && threadIdx.y == 0) {
        float a0 = alpha[0], a1 = alpha[1];
        float m = fmaxf(a0, a1);
        float e0 = expf(a0 - m), e1 = expf(a1 - m);
        float inv = 1.0f / (e0 + e1);
        g_alpha[0] = e0 * inv;
        g_alpha[1] = e1 * inv;
    }
    __shared__ float t[32][33];
    int bx = blockIdx.x * 32, by = blockIdx.y * 32;
    int tx = threadIdx.x, ty = threadIdx.y;
    t[ty][tx] = W[(size_t)(by + ty) * DD + bx + tx];
    __syncthreads();
    float v = t[tx][ty];
    int n = bx + ty, k = by + tx;
    g_WT[(size_t)n * DD + k] = __float2half(v);
}

// ---------------- single-product fp16 mma.sync GEMM ----------------------------
// C[M,512] = A[M,K](fp32 -> fp16 at fragment build) @ Bt[512,K]^T (fp16).
// CTA 256x128, 512 threads (16 warps), warp tile 16x128, kc=64, 2-stage.
// MODE 0: write C^T fp16 into CT1, ld1
// MODE 3: rows < M1 -> (CT1,ld1); rows >= M1 -> (CT2,ld2) at row-M1
// MODE 4 (FUSED): phase0 A1@B1 (K1) -> stash a0*acc fp16 in smem;
//                 phase1 A2@B2 (K2) -> Cf = relu(max(stash, a1*acc)+bias)
#define CTA_M 256
#define CTA_N 128
#define OFF_A32 0          // 256 x 64 fp32 = 64 KB
#define OFF_B   65536      // 128 x 64 fp16 = 16 KB
#define STAGE   81920
#define SMEM_MAIN (2 * STAGE)            // 160 KB (mainloop)
#define LPITCH  260                       // fp16 low-stash row pitch (bytes)
#define SMEM_FUSED (SMEM_MAIN + 256 * LPITCH)   // 225 KB

template<int MODE>
__global__ __launch_bounds__(512, 1)
void gemm_mma(const float* __restrict__ A1, const float* __restrict__ A2, int M1,
              const __half* __restrict__ B1, const __half* __restrict__ B2,
              int K1, int K2,
              float* __restrict__ Cf,
              __half* __restrict__ CT1, int ld1,
              __half* __restrict__ CT2, int ld2,
              const float* __restrict__ bias)
{
    extern __shared__ char smem[];
    const uint32_t sb = smem_u32(smem);
    const int tid = threadIdx.x;
    const int wid = tid >> 5, lid = tid & 31;
    const int brow = blockIdx.y * CTA_M, bcol = blockIdx.x * CTA_N;
    const int wm = wid * 16;                 // 16 warps, one 16-row band each
    const int grp = lid >> 2, ctid = lid & 3;

    // B ldmatrix lane geometry (128B rows, XOR swizzle)
    const int lb_row = (lid & 7) + ((lid >> 4) << 3);
    const int lb_col = ((lid >> 3) & 1) << 4;

    float acc[16][4];
    #pragma unroll
    for (int j = 0; j < 16; j++)
        #pragma unroll
        for (int q = 0; q < 4; q++) acc[j][q] = 0.0f;

    // A fp32: 256 rows x 64 f32 = 4096 16B-chunks; 8/thread.
    // B fp16: 128 rows x 64 halves (128B/row) = 1024 chunks; 2/thread.
    #define CPA(sidx, kt, APTR, BPTR, KROW) do { \
        uint32_t abse = sb + (uint32_t)(sidx) * STAGE; \
        _Pragma("unroll") \
        for (int r = 0; r < 8; r++) { \
            int idx = tid + (r << 9); \
            int row = idx >> 4, c = idx & 15; \
            uint32_t dst = abse + OFF_A32 + row * 256 + (uint32_t)((c ^ ((row & 7) << 1)) << 4); \
            cp16(dst, (APTR) + (size_t)row * (KROW) + (kt) + (c << 2)); \
        } \
        _Pragma("unroll") \
        for (int r = 0; r < 2; r++) { \
            int idx = tid + (r << 9); \
            int row = idx >> 3, c = idx & 7; \
            uint32_t dst = abse + OFF_B + row * 128 + (uint32_t)((c ^ (row & 7)) << 4); \
            cp16(dst, (BPTR) + (size_t)(bcol + row) * (KROW) + (kt) + (c << 3)); \
        } } while (0)

    #define RUN_PASS(APTR, BPTR, KROW, NT) do { \
        CPA(0, 0,  APTR, BPTR, KROW); CP_COMMIT(); \
        CPA(1, 64, APTR, BPTR, KROW); CP_COMMIT(); \
        for (int it = 0; it < (NT); it++) { \
            const int cs = it & 1; \
            const uint32_t cbase = sb + (uint32_t)cs * STAGE; \
            if (it + 1 < (NT)) { CP_WAIT1(); } else { CP_WAIT0(); } \
            __syncthreads(); \
            _Pragma("unroll") \
            for (int ks = 0; ks < 4; ks++) { \
                uint32_t ah[4]; \
                { \
                    const int r0_ = wm + grp; \
                    _Pragma("unroll") \
                    for (int u = 0; u < 4; u++) { \
                        const int rr = r0_ + (u & 1) * 8; \
                        const int kk = ks * 16 + ctid * 2 + (u >> 1) * 8; \
                        uint32_t addr = cbase + OFF_A32 + rr * 256 + \
                            (uint32_t)(((((kk >> 2) ^ ((rr & 7) << 1))) << 4) | ((kk & 3) << 2)); \
                        float f0, f1; \
                        asm volatile("ld.shared.v2.f32 {%0,%1}, [%2];" \
                                     : "=f"(f0), "=f"(f1) : "r"(addr)); \
                        __half2 hh = __floats2half2_rn(f0, f1); \
                        ah[u] = reinterpret_cast<uint32_t&>(hh); \
                    } \
                } \
                _Pragma("unroll") \
                for (int c = 0; c < 4; c++) { \
                    uint32_t bh[2][4]; \
                    _Pragma("unroll") \
                    for (int p = 0; p < 2; p++) { \
                        const int prow = lb_row + (c * 2 + p) * 16; \
                        uint32_t boff = (uint32_t)(prow * 128 + \
                                         ((lb_col + ks * 32) ^ ((prow & 7) << 4))); \
                        ldsm_x4(bh[p], cbase + OFF_B + boff); \
                    } \
                    _Pragma("unroll") \
                    for (int p = 0; p < 2; p++) \
                        _Pragma("unroll") \
                        for (int h = 0; h < 2; h++) \
                            mma16816(acc[c * 4 + p * 2 + h], ah, \
                                     bh[p][h * 2], bh[p][h * 2 + 1]); \
                } \
            } \
            __syncthreads(); \
            if (it + 2 < (NT)) { \
                CPA(cs, (it + 2) << 6, APTR, BPTR, KROW); \
                CP_COMMIT(); \
            } \
        } } while (0)

    if (MODE == 0 || MODE == 3) {
        const float* Ab;
        if (MODE == 3 && brow >= M1) Ab = A2 + (size_t)(brow - M1) * K1;
        else                         Ab = A1 + (size_t)brow * K1;
        RUN_PASS(Ab, B1, K1, (K1 >> 6));

        // ---- transpose-store epilogue (fp16) ----
        #pragma unroll
        for (int j = 0; j < 16; j++) {
            const int c0 = bcol + j * 8 + ctid * 2;
            #pragma unroll
            for (int q = 0; q < 4; q++) {
                const int mm = brow + wm + grp + (q >> 1) * 8;
                const int cc = c0 + (q & 1);
                __half h = __float2half(acc[j][q]);
                if (MODE == 0 || mm < M1) {
                    CT1[(size_t)cc * ld1 + mm] = h;
                } else {
                    CT2[(size_t)cc * ld2 + (mm - M1)] = h;
                }
            }
        }
    } else {   // MODE 4: fused low/high
        RUN_PASS(A1 + (size_t)brow * K1, B1, K1, (K1 >> 6));

        // stash a0*acc as fp16 (per-thread private roundtrip; no sync needed)
        const float a0 = g_alpha[0];
        #pragma unroll
        for (int j = 0; j < 16; j++) {
            const int cw = (j * 8 + ctid * 2) * 2;       // byte offset in row
            char* r0p = smem + SMEM_MAIN + (wm + grp) * LPITCH + cw;
            char* r1p = smem + SMEM_MAIN + (wm + grp + 8) * LPITCH + cw;
            *reinterpret_cast<__half2*>(r0p) =
                __floats2half2_rn(a0 * acc[j][0], a0 * acc[j][1]);
            *reinterpret_cast<__half2*>(r1p) =
                __floats2half2_rn(a0 * acc[j][2], a0 * acc[j][3]);
            acc[j][0] = acc[j][1] = acc[j][2] = acc[j][3] = 0.0f;
        }

        RUN_PASS(A2 + (size_t)brow * K2, B2, K2, (K2 >> 6));

        // fused epilogue: relu(max(low, a1*acc) + bias)
        const float a1v = g_alpha[1];
        const int m0 = brow + wm + grp;
        #pragma unroll
        for (int j = 0; j < 16; j++) {
            const int cw = (j * 8 + ctid * 2) * 2;
            const int c0 = bcol + j * 8 + ctid * 2;
            __half2 l01 = *reinterpret_cast<const __half2*>(
                smem + SMEM_MAIN + (wm + grp) * LPITCH + cw);
            __half2 l23 = *reinterpret_cast<const __half2*>(
                smem + SMEM_MAIN + (wm + grp + 8) * LPITCH + cw);
            float2 bb = *reinterpret_cast<const float2*>(bias + c0);
            float2 v0, v1;
            v0.x = fmaxf(fmaxf(__half2float(l01.x), a1v * acc[j][0]) + bb.x, 0.0f);
            v0.y = fmaxf(fmaxf(__half2float(l01.y), a1v * acc[j][1]) + bb.y, 0.0f);
            v1.x = fmaxf(fmaxf(__half2float(l23.x), a1v * acc[j][2]) + bb.x, 0.0f);
            v1.y = fmaxf(fmaxf(__half2float(l23.y), a1v * acc[j][3]) + bb.y, 0.0f);
            *reinterpret_cast<float2*>(Cf + (size_t)m0 * DD + c0) = v0;
            *reinterpret_cast<float2*>(Cf + (size_t)(m0 + 8) * DD + c0) = v1;
        }
    }
    #undef CPA
    #undef RUN_PASS
}

// ---------------- host launch ----------------------------------------------------
extern "C" void kernel_launch(void* const* d_in, const int* in_sizes, int n_in,
                              void* d_out, int out_size)
{
    const float* x     = (const float*)d_in[0];
    const float* W     = (const float*)d_in[1];
    const float* alpha = (const float*)d_in[2];
    const float* bias  = (const float*)d_in[3];
    const float* s0    = (const float*)d_in[4];
    const float* s1    = (const float*)d_in[5];
    const float* s2    = (const float*)d_in[6];
    const float* s3    = (const float*)d_in[7];
    float* out = (float*)d_out;

    __half *WT, *pT, *t1, *t3;
    cudaGetSymbolAddress((void**)&WT, g_WT);
    cudaGetSymbolAddress((void**)&pT, g_preT);
    cudaGetSymbolAddress((void**)&t1, g_t1T);
    cudaGetSymbolAddress((void**)&t3, g_t3T);

    static bool attr_done = false;
    if (!attr_done) {
        cudaFuncSetAttribute(gemm_mma<0>, cudaFuncAttributeMaxDynamicSharedMemorySize, SMEM_FUSED);
        cudaFuncSetAttribute(gemm_mma<3>, cudaFuncAttributeMaxDynamicSharedMemorySize, SMEM_FUSED);
        cudaFuncSetAttribute(gemm_mma<4>, cudaFuncAttributeMaxDynamicSharedMemorySize, SMEM_FUSED);
        attr_done = true;
    }

    wt_split_kernel<<<dim3(16, 16), dim3(32, 32)>>>(W, alpha);

    const dim3 grid(DD / CTA_N, NN / CTA_M);   // (4, 32) = 128 CTAs

    // pre^T = (x @ W)^T (fp16)
    gemm_mma<0><<<grid, 512, SMEM_MAIN>>>(
        x, nullptr, NN, WT, nullptr, DD, 0,
        nullptr, pT, NN, nullptr, 0, nullptr);
    // merged: t1^T (rows<2048 from s1) + t3^T (rows>=2048 from s3)
    gemm_mma<3><<<grid, 512, SMEM_MAIN>>>(
        s1, s3, KF, pT, nullptr, NN, 0,
        nullptr, t1, KF, t3, KH, nullptr);
    // FUSED: out = relu(max(a0*(s0@t1), a1*(s2@t3)) + bias)
    gemm_mma<4><<<grid, 512, SMEM_FUSED>>>(
        s0, s2, 0, t1, t3, KF, KH,
        out, nullptr, 0, nullptr, 0, bias);
}